// round 3
// baseline (speedup 1.0000x reference)
#include <cuda_runtime.h>
#include <cstdint>
#include <cstddef>

#define NN 8192
#define MM 20000
#define DD 1024
#define YY 256

// Scratch (no cudaMalloc allowed): kernel matrix + row norms.
__device__ float g_kmat[(size_t)NN * (size_t)MM];
__device__ float g_xsq[NN];
__device__ float g_zsq[MM];

// ---- packed f32x2 helpers (ptxas never emits FFMA2 from C++; PTX only) ----
__device__ __forceinline__ unsigned long long pack2(float lo, float hi) {
    unsigned long long r;
    unsigned int l = __float_as_uint(lo), h = __float_as_uint(hi);
    asm("mov.b64 %0, {%1, %2};" : "=l"(r) : "r"(l), "r"(h));
    return r;
}
__device__ __forceinline__ void unpack2(unsigned long long p, float& lo, float& hi) {
    unsigned int l, h;
    asm("mov.b64 {%0, %1}, %2;" : "=r"(l), "=r"(h) : "l"(p));
    lo = __uint_as_float(l);
    hi = __uint_as_float(h);
}
__device__ __forceinline__ void ffma2(unsigned long long& d, unsigned long long a,
                                      unsigned long long b) {
    asm("fma.rn.f32x2 %0, %1, %2, %3;" : "=l"(d) : "l"(a), "l"(b), "l"(d));
}

// ---- row squared-norms: one block per row, 128 threads ----
__global__ void rownorm_kernel(const float* __restrict__ X, int dcols, int which) {
    int row = blockIdx.x;
    const float4* p = reinterpret_cast<const float4*>(X + (size_t)row * dcols);
    float s = 0.f;
    int n4 = dcols >> 2;
    for (int i = threadIdx.x; i < n4; i += blockDim.x) {
        float4 v = p[i];
        s = fmaf(v.x, v.x, s); s = fmaf(v.y, v.y, s);
        s = fmaf(v.z, v.z, s); s = fmaf(v.w, v.w, s);
    }
#pragma unroll
    for (int o = 16; o; o >>= 1) s += __shfl_xor_sync(0xffffffffu, s, o);
    __shared__ float ws[4];
    int lane = threadIdx.x & 31, w = threadIdx.x >> 5;
    if (lane == 0) ws[w] = s;
    __syncthreads();
    if (threadIdx.x == 0) {
        float t = ws[0] + ws[1] + ws[2] + ws[3];
        if (which) g_zsq[row] = t; else g_xsq[row] = t;
    }
}

// ---- GEMM1 + epilogue: kmat[n,m] = exp(-sqrt(|x|^2+|z|^2-2 x.z)/bw) ----
// 128x128 tile, BK=8, 256 threads, 8x8 per thread, f32x2 accumulators.
__global__ __launch_bounds__(256)
void kmat_kernel(const float* __restrict__ A, const float* __restrict__ B,
                 const int* __restrict__ bwp) {
    __shared__ float As[8][132];
    __shared__ float Bs[8][132];

    const int tid = threadIdx.x;
    const int nBase = blockIdx.y * 128;
    const int mBase = blockIdx.x * 128;

    const int lr = tid >> 1;          // 0..127
    const int lc = (tid & 1) << 2;    // 0 or 4

    const float* Ap = A + (size_t)(nBase + lr) * DD + lc;
    const int gm = mBase + lr;
    const bool mok = (gm < MM);
    const float* Bp = B + (size_t)(mok ? gm : 0) * DD + lc;

    const int tRow = tid >> 4;        // 0..15
    const int tCol = tid & 15;        // 0..15

    unsigned long long acc[4][8];
#pragma unroll
    for (int i = 0; i < 4; ++i)
#pragma unroll
        for (int j = 0; j < 8; ++j) acc[i][j] = 0ull;

    for (int kk = 0; kk < DD; kk += 8) {
        float4 av = *reinterpret_cast<const float4*>(Ap + kk);
        float4 bv = mok ? *reinterpret_cast<const float4*>(Bp + kk)
                        : make_float4(0.f, 0.f, 0.f, 0.f);
        __syncthreads();
        As[lc + 0][lr] = av.x; As[lc + 1][lr] = av.y;
        As[lc + 2][lr] = av.z; As[lc + 3][lr] = av.w;
        Bs[lc + 0][lr] = bv.x; Bs[lc + 1][lr] = bv.y;
        Bs[lc + 2][lr] = bv.z; Bs[lc + 3][lr] = bv.w;
        __syncthreads();
#pragma unroll
        for (int k = 0; k < 8; ++k) {
            ulonglong2 a01 = *reinterpret_cast<const ulonglong2*>(&As[k][tRow * 8]);
            ulonglong2 a23 = *reinterpret_cast<const ulonglong2*>(&As[k][tRow * 8 + 4]);
            float4 b0 = *reinterpret_cast<const float4*>(&Bs[k][tCol * 8]);
            float4 b1 = *reinterpret_cast<const float4*>(&Bs[k][tCol * 8 + 4]);
            unsigned long long a2[4] = { a01.x, a01.y, a23.x, a23.y };
            unsigned long long b2[8] = {
                pack2(b0.x, b0.x), pack2(b0.y, b0.y), pack2(b0.z, b0.z), pack2(b0.w, b0.w),
                pack2(b1.x, b1.x), pack2(b1.y, b1.y), pack2(b1.z, b1.z), pack2(b1.w, b1.w)
            };
#pragma unroll
            for (int i = 0; i < 4; ++i)
#pragma unroll
                for (int j = 0; j < 8; ++j) ffma2(acc[i][j], a2[i], b2[j]);
        }
    }

    // bandwidth may arrive as int32 or float32 bits — disambiguate heuristically
    int ibw = *bwp;
    float bwf = (ibw > 0 && ibw < 1000000) ? (float)ibw : __int_as_float(ibw);
    float inv_bw = 1.0f / bwf;

    float xs[8];
#pragma unroll
    for (int r = 0; r < 8; ++r) xs[r] = g_xsq[nBase + tRow * 8 + r];

    const int mcol0 = mBase + tCol * 8;
    float zs[8];
#pragma unroll
    for (int j = 0; j < 8; ++j) zs[j] = (mcol0 + j < MM) ? g_zsq[mcol0 + j] : 0.f;

    const bool fullm = (mBase + 128 <= MM);
#pragma unroll
    for (int i = 0; i < 4; ++i) {
        float vals[2][8];
#pragma unroll
        for (int j = 0; j < 8; ++j) {
            float dlo, dhi;
            unpack2(acc[i][j], dlo, dhi);
            float d2lo = xs[2 * i]     + zs[j] - 2.f * dlo;
            float d2hi = xs[2 * i + 1] + zs[j] - 2.f * dhi;
            vals[0][j] = expf(-sqrtf(fmaxf(d2lo, 0.f)) * inv_bw);
            vals[1][j] = expf(-sqrtf(fmaxf(d2hi, 0.f)) * inv_bw);
        }
#pragma unroll
        for (int h = 0; h < 2; ++h) {
            int n = nBase + tRow * 8 + 2 * i + h;
            float* dst = g_kmat + (size_t)n * MM + mcol0;
            if (fullm) {
                *reinterpret_cast<float4*>(dst)     =
                    make_float4(vals[h][0], vals[h][1], vals[h][2], vals[h][3]);
                *reinterpret_cast<float4*>(dst + 4) =
                    make_float4(vals[h][4], vals[h][5], vals[h][6], vals[h][7]);
            } else {
#pragma unroll
                for (int j = 0; j < 8; ++j)
                    if (mcol0 + j < MM) dst[j] = vals[h][j];
            }
        }
    }
}

// ---- GEMM2: out[n,y] = sum_m kmat[n,m] * W[m,y] ----
// 128x128 tile (Y=256 -> 2 col tiles), BK=8, 256 threads, 8x8 per thread.
__global__ __launch_bounds__(256)
void out_kernel(const float* __restrict__ W, float* __restrict__ Out) {
    __shared__ float As[8][132];
    __shared__ float Bs[8][132];

    const int tid = threadIdx.x;
    const int nBase = blockIdx.y * 128;
    const int yBase = blockIdx.x * 128;

    const int alr = tid >> 1;
    const int alc = (tid & 1) << 2;
    const float* Ap = g_kmat + (size_t)(nBase + alr) * MM + alc;

    const int blr = tid >> 5;           // 0..7
    const int blc = (tid & 31) << 2;    // 0..124
    const float* Bp = W + (size_t)blr * YY + yBase + blc;

    const int tRow = tid >> 4;
    const int tCol = tid & 15;

    unsigned long long acc[4][8];
#pragma unroll
    for (int i = 0; i < 4; ++i)
#pragma unroll
        for (int j = 0; j < 8; ++j) acc[i][j] = 0ull;

    for (int kk = 0; kk < MM; kk += 8) {
        float4 av = *reinterpret_cast<const float4*>(Ap + kk);
        float4 bv = *reinterpret_cast<const float4*>(Bp + (size_t)kk * YY);
        __syncthreads();
        As[alc + 0][alr] = av.x; As[alc + 1][alr] = av.y;
        As[alc + 2][alr] = av.z; As[alc + 3][alr] = av.w;
        *reinterpret_cast<float4*>(&Bs[blr][blc]) = bv;
        __syncthreads();
#pragma unroll
        for (int k = 0; k < 8; ++k) {
            ulonglong2 a01 = *reinterpret_cast<const ulonglong2*>(&As[k][tRow * 8]);
            ulonglong2 a23 = *reinterpret_cast<const ulonglong2*>(&As[k][tRow * 8 + 4]);
            float4 b0 = *reinterpret_cast<const float4*>(&Bs[k][tCol * 8]);
            float4 b1 = *reinterpret_cast<const float4*>(&Bs[k][tCol * 8 + 4]);
            unsigned long long a2[4] = { a01.x, a01.y, a23.x, a23.y };
            unsigned long long b2[8] = {
                pack2(b0.x, b0.x), pack2(b0.y, b0.y), pack2(b0.z, b0.z), pack2(b0.w, b0.w),
                pack2(b1.x, b1.x), pack2(b1.y, b1.y), pack2(b1.z, b1.z), pack2(b1.w, b1.w)
            };
#pragma unroll
            for (int i = 0; i < 4; ++i)
#pragma unroll
                for (int j = 0; j < 8; ++j) ffma2(acc[i][j], a2[i], b2[j]);
        }
    }

#pragma unroll
    for (int i = 0; i < 4; ++i) {
        float v[2][8];
#pragma unroll
        for (int j = 0; j < 8; ++j) unpack2(acc[i][j], v[0][j], v[1][j]);
#pragma unroll
        for (int h = 0; h < 2; ++h) {
            int n = nBase + tRow * 8 + 2 * i + h;
            float* dst = Out + (size_t)n * YY + yBase + tCol * 8;
            *reinterpret_cast<float4*>(dst)     = make_float4(v[h][0], v[h][1], v[h][2], v[h][3]);
            *reinterpret_cast<float4*>(dst + 4) = make_float4(v[h][4], v[h][5], v[h][6], v[h][7]);
        }
    }
}

extern "C" void kernel_launch(void* const* d_in, const int* in_sizes, int n_in,
                              void* d_out, int out_size) {
    (void)in_sizes; (void)n_in; (void)out_size;
    const float* batch   = (const float*)d_in[0];
    const float* centers = (const float*)d_in[1];
    const float* weight  = (const float*)d_in[2];
    const int*   bwp     = (const int*)d_in[3];
    float* out = (float*)d_out;

    rownorm_kernel<<<NN, 128>>>(batch, DD, 0);
    rownorm_kernel<<<MM, 128>>>(centers, DD, 1);

    dim3 g1((MM + 127) / 128, NN / 128);
    kmat_kernel<<<g1, 256>>>(batch, centers, bwp);

    dim3 g2(YY / 128, NN / 128);
    out_kernel<<<g2, 256>>>(weight, out);
}

// round 5
// speedup vs baseline: 4.4846x; 4.4846x over previous
#include <cuda_runtime.h>
#include <cuda_bf16.h>
#include <cstdint>
#include <cstddef>

#define NN 8192
#define MM 20000
#define DD 1024
#define YY 256

#define ST 80  // padded SMEM row stride in bytes (64B data + 16B pad)

// Scratch (no cudaMalloc allowed)
__device__ float g_kmat[(size_t)NN * (size_t)MM];      // tf32-rounded kernel matrix
__device__ float g_wt[(size_t)YY * (size_t)MM];        // W^T, tf32-rounded
__device__ float g_xsq[NN];
__device__ float g_zsq[MM];
__device__ __nv_bfloat16 g_abf[(size_t)NN * DD];
__device__ __nv_bfloat16 g_bbf[(size_t)MM * DD];

// ---------------- helpers ----------------
__device__ __forceinline__ uint32_t s2u(const void* p) {
    return (uint32_t)__cvta_generic_to_shared(p);
}
__device__ __forceinline__ float ex2_ap(float x) {
    float r; asm("ex2.approx.f32 %0, %1;" : "=f"(r) : "f"(x)); return r;
}
__device__ __forceinline__ float sqrt_ap(float x) {
    float r; asm("sqrt.approx.f32 %0, %1;" : "=f"(r) : "f"(x)); return r;
}
__device__ __forceinline__ uint32_t to_tf32(float x) {
    uint32_t r; asm("cvt.rna.tf32.f32 %0, %1;" : "=r"(r) : "f"(x)); return r;
}
__device__ __forceinline__ void cp16(uint32_t dst, const void* src) {
    asm volatile("cp.async.cg.shared.global [%0], [%1], 16;" :: "r"(dst), "l"(src));
}
__device__ __forceinline__ void cp_commit() {
    asm volatile("cp.async.commit_group;" ::: "memory");
}
template <int N>
__device__ __forceinline__ void cp_wait() {
    asm volatile("cp.async.wait_group %0;" :: "n"(N) : "memory");
}
__device__ __forceinline__ void ldm_x4(uint32_t& r0, uint32_t& r1, uint32_t& r2,
                                       uint32_t& r3, uint32_t addr) {
    asm volatile("ldmatrix.sync.aligned.m8n8.x4.shared.b16 {%0,%1,%2,%3}, [%4];"
                 : "=r"(r0), "=r"(r1), "=r"(r2), "=r"(r3) : "r"(addr));
}
__device__ __forceinline__ void ldm_x2(uint32_t& r0, uint32_t& r1, uint32_t addr) {
    asm volatile("ldmatrix.sync.aligned.m8n8.x2.shared.b16 {%0,%1}, [%2];"
                 : "=r"(r0), "=r"(r1) : "r"(addr));
}
__device__ __forceinline__ void mma_bf16(float* c, uint32_t a0, uint32_t a1,
                                         uint32_t a2, uint32_t a3,
                                         uint32_t b0, uint32_t b1) {
    asm volatile(
        "mma.sync.aligned.m16n8k16.row.col.f32.bf16.bf16.f32 "
        "{%0,%1,%2,%3}, {%4,%5,%6,%7}, {%8,%9}, {%0,%1,%2,%3};"
        : "+f"(c[0]), "+f"(c[1]), "+f"(c[2]), "+f"(c[3])
        : "r"(a0), "r"(a1), "r"(a2), "r"(a3), "r"(b0), "r"(b1));
}
__device__ __forceinline__ void mma_tf32(float* c, uint32_t a0, uint32_t a1,
                                         uint32_t a2, uint32_t a3,
                                         uint32_t b0, uint32_t b1) {
    asm volatile(
        "mma.sync.aligned.m16n8k8.row.col.f32.tf32.tf32.f32 "
        "{%0,%1,%2,%3}, {%4,%5,%6,%7}, {%8,%9}, {%0,%1,%2,%3};"
        : "+f"(c[0]), "+f"(c[1]), "+f"(c[2]), "+f"(c[3])
        : "r"(a0), "r"(a1), "r"(a2), "r"(a3), "r"(b0), "r"(b1));
}

// ---- fp32 -> bf16 conversion ----
__global__ void cvt_kernel(const float* __restrict__ src,
                           __nv_bfloat16* __restrict__ dst, int n4) {
    int i = blockIdx.x * blockDim.x + threadIdx.x;
    if (i < n4) {
        float4 v = reinterpret_cast<const float4*>(src)[i];
        __nv_bfloat162 lo = __floats2bfloat162_rn(v.x, v.y);
        __nv_bfloat162 hi = __floats2bfloat162_rn(v.z, v.w);
        uint2 o;
        o.x = *reinterpret_cast<unsigned*>(&lo);
        o.y = *reinterpret_cast<unsigned*>(&hi);
        reinterpret_cast<uint2*>(dst)[i] = o;
    }
}

// ---- row squared-norms (fp32 exact) ----
__global__ void rownorm_kernel(const float* __restrict__ X, int dcols, int which) {
    int row = blockIdx.x;
    const float4* p = reinterpret_cast<const float4*>(X + (size_t)row * dcols);
    float s = 0.f;
    int n4 = dcols >> 2;
    for (int i = threadIdx.x; i < n4; i += blockDim.x) {
        float4 v = p[i];
        s = fmaf(v.x, v.x, s); s = fmaf(v.y, v.y, s);
        s = fmaf(v.z, v.z, s); s = fmaf(v.w, v.w, s);
    }
#pragma unroll
    for (int o = 16; o; o >>= 1) s += __shfl_xor_sync(0xffffffffu, s, o);
    __shared__ float ws[4];
    int lane = threadIdx.x & 31, w = threadIdx.x >> 5;
    if (lane == 0) ws[w] = s;
    __syncthreads();
    if (threadIdx.x == 0) {
        float t = ws[0] + ws[1] + ws[2] + ws[3];
        if (which) g_zsq[row] = t; else g_xsq[row] = t;
    }
}

// ---- transpose W [MM][YY] -> Wt [YY][MM], rounding to tf32 ----
__global__ void wt_kernel(const float* __restrict__ W) {
    __shared__ float t[32][33];
    int bx = blockIdx.x * 32;  // y block
    int by = blockIdx.y * 32;  // m block
    int tx = threadIdx.x, ty = threadIdx.y;
#pragma unroll
    for (int q = 0; q < 4; ++q)
        t[ty + q * 8][tx] = W[(size_t)(by + ty + q * 8) * YY + bx + tx];
    __syncthreads();
#pragma unroll
    for (int q = 0; q < 4; ++q) {
        float v = t[tx][ty + q * 8];
        reinterpret_cast<uint32_t*>(g_wt)[(size_t)(bx + ty + q * 8) * MM + by + tx] =
            to_tf32(v);
    }
}

// ============== GEMM1: bf16 mma.sync, fused Laplacian epilogue ==============
// 128x128x32 tile, 256 threads, 8 warps (2 row x 4 col), warp tile 64x32.
__device__ __forceinline__ void g1_copy(uint32_t aDst, uint32_t bDst, int kc,
                                        int tid, int nBase, int mBase) {
    int row = tid >> 1;
    int s0 = (tid & 1) * 2;
    const char* asrc = reinterpret_cast<const char*>(g_abf) +
                       ((size_t)(nBase + row) * DD) * 2 + (size_t)kc * 64;
    uint32_t ad = aDst + row * ST;
    cp16(ad + s0 * 16, asrc + s0 * 16);
    cp16(ad + (s0 + 1) * 16, asrc + (s0 + 1) * 16);
    int gm = mBase + row;
    if (gm >= MM) gm = MM - 1;
    const char* bsrc = reinterpret_cast<const char*>(g_bbf) +
                       ((size_t)gm * DD) * 2 + (size_t)kc * 64;
    uint32_t bd = bDst + row * ST;
    cp16(bd + s0 * 16, bsrc + s0 * 16);
    cp16(bd + (s0 + 1) * 16, bsrc + (s0 + 1) * 16);
    cp_commit();
}

__global__ __launch_bounds__(256)
void kmat_mma_kernel(const int* __restrict__ bwp) {
    __shared__ __align__(16) char sm[2 * (128 * ST + 128 * ST)];  // 40960B

    const int tid = threadIdx.x;
    const int l = tid & 31;
    const int wid = tid >> 5;
    const int wr = wid >> 2;   // 0..1
    const int wc = wid & 3;    // 0..3
    const int nBase = blockIdx.y * 128;
    const int mBase = blockIdx.x * 128;
    const uint32_t base = s2u(sm);
    const uint32_t STAGE = 128 * ST * 2;  // A+B per stage

    float c[4][4][4];
#pragma unroll
    for (int i = 0; i < 4; ++i)
#pragma unroll
        for (int j = 0; j < 4; ++j)
#pragma unroll
            for (int q = 0; q < 4; ++q) c[i][j][q] = 0.f;

    g1_copy(base, base + 128 * ST, 0, tid, nBase, mBase);

    const int NCH = DD / 32;  // 32
    for (int kc = 0; kc < NCH; ++kc) {
        if (kc + 1 < NCH) {
            uint32_t st = base + (uint32_t)((kc + 1) & 1) * STAGE;
            g1_copy(st, st + 128 * ST, kc + 1, tid, nBase, mBase);
            cp_wait<1>();
        } else {
            cp_wait<0>();
        }
        __syncthreads();
        uint32_t aS = base + (uint32_t)(kc & 1) * STAGE;
        uint32_t bS = aS + 128 * ST;
#pragma unroll
        for (int ks = 0; ks < 2; ++ks) {
            int koff = ks * 32;
            uint32_t a[4][4];
#pragma unroll
            for (int i = 0; i < 4; ++i)
                ldm_x4(a[i][0], a[i][1], a[i][2], a[i][3],
                       aS + (wr * 64 + i * 16 + (l & 15)) * ST + koff + ((l >> 4) << 4));
            uint32_t b[4][2];
#pragma unroll
            for (int j = 0; j < 4; ++j)
                ldm_x2(b[j][0], b[j][1],
                       bS + (wc * 32 + j * 8 + (l & 7)) * ST + koff + (((l >> 3) & 1) << 4));
#pragma unroll
            for (int i = 0; i < 4; ++i)
#pragma unroll
                for (int j = 0; j < 4; ++j)
                    mma_bf16(c[i][j], a[i][0], a[i][1], a[i][2], a[i][3],
                             b[j][0], b[j][1]);
        }
        __syncthreads();
    }

    // ---- epilogue: exp(-sqrt(|x|^2+|z|^2-2 dot)/bw), round to tf32, store ----
    int ibw = *bwp;
    float bwf = (ibw > 0 && ibw < 1000000) ? (float)ibw : __int_as_float(ibw);
    const float negscale = -1.44269504088896f / bwf;

#pragma unroll
    for (int i = 0; i < 4; ++i) {
        int r0 = nBase + wr * 64 + i * 16 + (l >> 2);
        float xs0 = g_xsq[r0];
        float xs1 = g_xsq[r0 + 8];
#pragma unroll
        for (int j = 0; j < 4; ++j) {
            int col = mBase + wc * 32 + j * 8 + 2 * (l & 3);
            if (col < MM) {
                float2 zz = *reinterpret_cast<const float2*>(&g_zsq[col]);
                float d00 = fmaf(-2.f, c[i][j][0], xs0 + zz.x);
                float d01 = fmaf(-2.f, c[i][j][1], xs0 + zz.y);
                float d10 = fmaf(-2.f, c[i][j][2], xs1 + zz.x);
                float d11 = fmaf(-2.f, c[i][j][3], xs1 + zz.y);
                uint2 o0, o1;
                o0.x = to_tf32(ex2_ap(sqrt_ap(fmaxf(d00, 0.f)) * negscale));
                o0.y = to_tf32(ex2_ap(sqrt_ap(fmaxf(d01, 0.f)) * negscale));
                o1.x = to_tf32(ex2_ap(sqrt_ap(fmaxf(d10, 0.f)) * negscale));
                o1.y = to_tf32(ex2_ap(sqrt_ap(fmaxf(d11, 0.f)) * negscale));
                *reinterpret_cast<uint2*>(g_kmat + (size_t)r0 * MM + col) = o0;
                *reinterpret_cast<uint2*>(g_kmat + (size_t)(r0 + 8) * MM + col) = o1;
            }
        }
    }
}

// ============== GEMM2: tf32 mma.sync out = kmat @ W ==============
// 128(n) x 64(y) tile, BK=16 f32, 256 threads, 8 warps (4 row x 2 col),
// warp tile 32x32.
__device__ __forceinline__ void g2_copy(uint32_t aDst, uint32_t bDst, int kc,
                                        int tid, int nBase, int yBase) {
    {
        int row = tid >> 1;
        int s0 = (tid & 1) * 2;
        const char* asrc = reinterpret_cast<const char*>(g_kmat) +
                           ((size_t)(nBase + row) * MM + (size_t)kc * 16) * 4;
        uint32_t ad = aDst + row * ST;
        cp16(ad + s0 * 16, asrc + s0 * 16);
        cp16(ad + (s0 + 1) * 16, asrc + (s0 + 1) * 16);
    }
    {
        int row = tid >> 2;
        int s = tid & 3;
        const char* bsrc = reinterpret_cast<const char*>(g_wt) +
                           ((size_t)(yBase + row) * MM + (size_t)kc * 16) * 4;
        cp16(bDst + row * ST + s * 16, bsrc + s * 16);
    }
    cp_commit();
}

__global__ __launch_bounds__(256)
void out_mma_kernel(float* __restrict__ Out) {
    __shared__ __align__(16) char sm[2 * (128 * ST + 64 * ST)];  // 30720B

    const int tid = threadIdx.x;
    const int l = tid & 31;
    const int wid = tid >> 5;
    const int wr = wid >> 1;   // 0..3
    const int wc = wid & 1;    // 0..1
    const int nBase = blockIdx.y * 128;
    const int yBase = blockIdx.x * 64;
    const uint32_t base = s2u(sm);
    const uint32_t STAGE = (128 + 64) * ST;

    float c[2][4][4];
#pragma unroll
    for (int i = 0; i < 2; ++i)
#pragma unroll
        for (int j = 0; j < 4; ++j)
#pragma unroll
            for (int q = 0; q < 4; ++q) c[i][j][q] = 0.f;

    g2_copy(base, base + 128 * ST, 0, tid, nBase, yBase);

    const int NCH = MM / 16;  // 1250
    for (int kc = 0; kc < NCH; ++kc) {
        if (kc + 1 < NCH) {
            uint32_t st = base + (uint32_t)((kc + 1) & 1) * STAGE;
            g2_copy(st, st + 128 * ST, kc + 1, tid, nBase, yBase);
            cp_wait<1>();
        } else {
            cp_wait<0>();
        }
        __syncthreads();
        uint32_t aS = base + (uint32_t)(kc & 1) * STAGE;
        uint32_t bS = aS + 128 * ST;
#pragma unroll
        for (int ks = 0; ks < 2; ++ks) {
            int koff = ks * 32;
            uint32_t a[2][4];
#pragma unroll
            for (int i = 0; i < 2; ++i)
                ldm_x4(a[i][0], a[i][1], a[i][2], a[i][3],
                       aS + (wr * 32 + i * 16 + (l & 15)) * ST + koff + ((l >> 4) << 4));
            uint32_t b[4][2];
#pragma unroll
            for (int j = 0; j < 4; ++j)
                ldm_x2(b[j][0], b[j][1],
                       bS + (wc * 32 + j * 8 + (l & 7)) * ST + koff + (((l >> 3) & 1) << 4));
#pragma unroll
            for (int i = 0; i < 2; ++i)
#pragma unroll
                for (int j = 0; j < 4; ++j)
                    mma_tf32(c[i][j], a[i][0], a[i][1], a[i][2], a[i][3],
                             b[j][0], b[j][1]);
        }
        __syncthreads();
    }

#pragma unroll
    for (int i = 0; i < 2; ++i) {
        int r0 = nBase + wr * 32 + i * 16 + (l >> 2);
#pragma unroll
        for (int j = 0; j < 4; ++j) {
            int col = yBase + wc * 32 + j * 8 + 2 * (l & 3);
            *reinterpret_cast<float2*>(Out + (size_t)r0 * YY + col) =
                make_float2(c[i][j][0], c[i][j][1]);
            *reinterpret_cast<float2*>(Out + (size_t)(r0 + 8) * YY + col) =
                make_float2(c[i][j][2], c[i][j][3]);
        }
    }
}

extern "C" void kernel_launch(void* const* d_in, const int* in_sizes, int n_in,
                              void* d_out, int out_size) {
    (void)in_sizes; (void)n_in; (void)out_size;
    const float* batch   = (const float*)d_in[0];
    const float* centers = (const float*)d_in[1];
    const float* weight  = (const float*)d_in[2];
    const int*   bwp     = (const int*)d_in[3];
    float* out = (float*)d_out;

    // bf16 copies of inputs
    {
        __nv_bfloat16* abf_p = nullptr;
        __nv_bfloat16* bbf_p = nullptr;
        cudaGetSymbolAddress((void**)&abf_p, g_abf);
        cudaGetSymbolAddress((void**)&bbf_p, g_bbf);
        int nA4 = NN * DD / 4, nB4 = MM * DD / 4;
        cvt_kernel<<<(nA4 + 255) / 256, 256>>>(batch, abf_p, nA4);
        cvt_kernel<<<(nB4 + 255) / 256, 256>>>(centers, bbf_p, nB4);
    }

    rownorm_kernel<<<NN, 128>>>(batch, DD, 0);
    rownorm_kernel<<<MM, 128>>>(centers, DD, 1);

    {
        dim3 b(32, 8);
        dim3 g(YY / 32, MM / 32);  // 8 x 625
        wt_kernel<<<g, b>>>(weight);
    }

    dim3 g1((MM + 127) / 128, NN / 128);  // 157 x 64
    kmat_mma_kernel<<<g1, 256>>>(bwp);

    dim3 g2(YY / 64, NN / 128);  // 4 x 64
    out_mma_kernel<<<g2, 256>>>(out);
}

// round 8
// speedup vs baseline: 6.0681x; 1.3531x over previous
#include <cuda_runtime.h>
#include <cuda_bf16.h>
#include <cuda_fp16.h>
#include <cstdint>
#include <cstddef>

#define NN 8192
#define MM 20000
#define DD 1024
#define YY 256

#define ST 80  // padded SMEM row stride in bytes (64B data + 16B pad)

// Scratch (no cudaMalloc allowed)
__device__ __half g_kh[(size_t)NN * (size_t)MM];     // fp16 kernel matrix
__device__ __half g_wth[(size_t)YY * (size_t)MM];    // W^T fp16
__device__ float g_xsq[NN];
__device__ float g_zsq[MM];
__device__ __nv_bfloat16 g_abf[(size_t)NN * DD];
__device__ __nv_bfloat16 g_bbf[(size_t)MM * DD];

// ---------------- helpers ----------------
__device__ __forceinline__ uint32_t s2u(const void* p) {
    return (uint32_t)__cvta_generic_to_shared(p);
}
__device__ __forceinline__ float ex2_ap(float x) {
    float r; asm("ex2.approx.f32 %0, %1;" : "=f"(r) : "f"(x)); return r;
}
__device__ __forceinline__ float sqrt_ap(float x) {
    float r; asm("sqrt.approx.f32 %0, %1;" : "=f"(r) : "f"(x)); return r;
}
__device__ __forceinline__ void cp16(uint32_t dst, const void* src) {
    asm volatile("cp.async.cg.shared.global [%0], [%1], 16;" :: "r"(dst), "l"(src));
}
__device__ __forceinline__ void cp_commit() {
    asm volatile("cp.async.commit_group;" ::: "memory");
}
template <int N>
__device__ __forceinline__ void cp_wait() {
    asm volatile("cp.async.wait_group %0;" :: "n"(N) : "memory");
}
__device__ __forceinline__ void ldm_x4(uint32_t& r0, uint32_t& r1, uint32_t& r2,
                                       uint32_t& r3, uint32_t addr) {
    asm volatile("ldmatrix.sync.aligned.m8n8.x4.shared.b16 {%0,%1,%2,%3}, [%4];"
                 : "=r"(r0), "=r"(r1), "=r"(r2), "=r"(r3) : "r"(addr));
}
__device__ __forceinline__ void ldm_x2(uint32_t& r0, uint32_t& r1, uint32_t addr) {
    asm volatile("ldmatrix.sync.aligned.m8n8.x2.shared.b16 {%0,%1}, [%2];"
                 : "=r"(r0), "=r"(r1) : "r"(addr));
}
__device__ __forceinline__ void mma_bf16(float* c, uint32_t a0, uint32_t a1,
                                         uint32_t a2, uint32_t a3,
                                         uint32_t b0, uint32_t b1) {
    asm volatile(
        "mma.sync.aligned.m16n8k16.row.col.f32.bf16.bf16.f32 "
        "{%0,%1,%2,%3}, {%4,%5,%6,%7}, {%8,%9}, {%0,%1,%2,%3};"
        : "+f"(c[0]), "+f"(c[1]), "+f"(c[2]), "+f"(c[3])
        : "r"(a0), "r"(a1), "r"(a2), "r"(a3), "r"(b0), "r"(b1));
}
__device__ __forceinline__ void mma_f16(float* c, uint32_t a0, uint32_t a1,
                                        uint32_t a2, uint32_t a3,
                                        uint32_t b0, uint32_t b1) {
    asm volatile(
        "mma.sync.aligned.m16n8k16.row.col.f32.f16.f16.f32 "
        "{%0,%1,%2,%3}, {%4,%5,%6,%7}, {%8,%9}, {%0,%1,%2,%3};"
        : "+f"(c[0]), "+f"(c[1]), "+f"(c[2]), "+f"(c[3])
        : "r"(a0), "r"(a1), "r"(a2), "r"(a3), "r"(b0), "r"(b1));
}

// ---- fused fp32->bf16 conversion + row squared-norm (one pass) ----
__global__ void cvtnorm_kernel(const float* __restrict__ src,
                               __nv_bfloat16* __restrict__ dst,
                               float* __restrict__ nrm) {
    int row = blockIdx.x;
    const float4* p = reinterpret_cast<const float4*>(src + (size_t)row * DD);
    float4 v = p[threadIdx.x];  // 256 threads x float4 = 1024 elems
    __nv_bfloat162 lo = __floats2bfloat162_rn(v.x, v.y);
    __nv_bfloat162 hi = __floats2bfloat162_rn(v.z, v.w);
    uint2 o;
    o.x = *reinterpret_cast<unsigned*>(&lo);
    o.y = *reinterpret_cast<unsigned*>(&hi);
    reinterpret_cast<uint2*>(dst + (size_t)row * DD)[threadIdx.x] = o;

    float s = fmaf(v.x, v.x, fmaf(v.y, v.y, fmaf(v.z, v.z, v.w * v.w)));
#pragma unroll
    for (int off = 16; off; off >>= 1) s += __shfl_xor_sync(0xffffffffu, s, off);
    __shared__ float ws[8];
    int lane = threadIdx.x & 31, w = threadIdx.x >> 5;
    if (lane == 0) ws[w] = s;
    __syncthreads();
    if (threadIdx.x == 0) {
        float t = 0.f;
#pragma unroll
        for (int i = 0; i < 8; ++i) t += ws[i];
        nrm[row] = t;
    }
}

// ---- transpose W [MM][YY] -> Wt [YY][MM] in fp16 ----
__global__ void wth_kernel(const float* __restrict__ W) {
    __shared__ float t[32][33];
    int bx = blockIdx.x * 32;  // y block
    int by = blockIdx.y * 32;  // m block
    int tx = threadIdx.x, ty = threadIdx.y;
#pragma unroll
    for (int q = 0; q < 4; ++q)
        t[ty + q * 8][tx] = W[(size_t)(by + ty + q * 8) * YY + bx + tx];
    __syncthreads();
#pragma unroll
    for (int q = 0; q < 4; ++q) {
        float v = t[tx][ty + q * 8];
        g_wth[(size_t)(bx + ty + q * 8) * MM + by + tx] = __float2half_rn(v);
    }
}

// ============== GEMM1: bf16 mma.sync, fused Laplacian epilogue ==============
// 128x128x32 tile, 256 threads, 8 warps (2x4), warp tile 64x32, 3 stages.
#define NCH1 32
#define S1 (2 * 128 * ST)  // 20480 B per stage (A+B)
#define SMEM1 (3 * S1)

__device__ __forceinline__ void g1_copy(uint32_t stage, int kc,
                                        int tid, int nBase, int mBase) {
    int row = tid >> 1;
    int s0 = (tid & 1) * 2;
    const char* asrc = reinterpret_cast<const char*>(g_abf) +
                       ((size_t)(nBase + row) * DD) * 2 + (size_t)kc * 64;
    uint32_t ad = stage + row * ST;
    cp16(ad + s0 * 16, asrc + s0 * 16);
    cp16(ad + (s0 + 1) * 16, asrc + (s0 + 1) * 16);
    int gm = mBase + row;
    if (gm >= MM) gm = MM - 1;
    const char* bsrc = reinterpret_cast<const char*>(g_bbf) +
                       ((size_t)gm * DD) * 2 + (size_t)kc * 64;
    uint32_t bd = stage + 128 * ST + row * ST;
    cp16(bd + s0 * 16, bsrc + s0 * 16);
    cp16(bd + (s0 + 1) * 16, bsrc + (s0 + 1) * 16);
    cp_commit();
}

__global__ __launch_bounds__(256, 2)
void kmat_mma_kernel(const int* __restrict__ bwp) {
    extern __shared__ __align__(16) char sm1[];

    const int tid = threadIdx.x;
    const int l = tid & 31;
    const int wid = tid >> 5;
    const int wr = wid >> 2;   // 0..1
    const int wc = wid & 3;    // 0..3

    // CTA swizzle: groups of 8 n-blocks for L2 reuse
    const int GM = (MM + 127) / 128;  // 157 m-blocks
    int bid = blockIdx.x;
    int grp = bid / (8 * GM);
    int rem = bid % (8 * GM);
    const int nBase = (grp * 8 + (rem & 7)) * 128;
    const int mBase = (rem >> 3) * 128;

    const uint32_t base = s2u(sm1);

    float c[4][4][4];
#pragma unroll
    for (int i = 0; i < 4; ++i)
#pragma unroll
        for (int j = 0; j < 4; ++j)
#pragma unroll
            for (int q = 0; q < 4; ++q) c[i][j][q] = 0.f;

    g1_copy(base + 0 * S1, 0, tid, nBase, mBase);
    g1_copy(base + 1 * S1, 1, tid, nBase, mBase);

    for (int kc = 0; kc < NCH1; ++kc) {
        if (kc < NCH1 - 1) cp_wait<1>(); else cp_wait<0>();
        __syncthreads();
        if (kc + 2 < NCH1)
            g1_copy(base + (uint32_t)((kc + 2) % 3) * S1, kc + 2, tid, nBase, mBase);

        uint32_t aS = base + (uint32_t)(kc % 3) * S1;
        uint32_t bS = aS + 128 * ST;
#pragma unroll
        for (int ks = 0; ks < 2; ++ks) {
            int koff = ks * 32;
            uint32_t a[4][4];
#pragma unroll
            for (int i = 0; i < 4; ++i)
                ldm_x4(a[i][0], a[i][1], a[i][2], a[i][3],
                       aS + (wr * 64 + i * 16 + (l & 15)) * ST + koff + ((l >> 4) << 4));
            uint32_t b[4][2];
#pragma unroll
            for (int j = 0; j < 4; ++j)
                ldm_x2(b[j][0], b[j][1],
                       bS + (wc * 32 + j * 8 + (l & 7)) * ST + koff + (((l >> 3) & 1) << 4));
#pragma unroll
            for (int i = 0; i < 4; ++i)
#pragma unroll
                for (int j = 0; j < 4; ++j)
                    mma_bf16(c[i][j], a[i][0], a[i][1], a[i][2], a[i][3],
                             b[j][0], b[j][1]);
        }
    }

    // ---- epilogue: exp(-sqrt(|x|^2+|z|^2-2 dot)/bw) -> fp16 kmat ----
    int ibw = *bwp;
    float bwf = (ibw > 0 && ibw < 1000000) ? (float)ibw : __int_as_float(ibw);
    const float negscale = -1.44269504088896f / bwf;

#pragma unroll
    for (int i = 0; i < 4; ++i) {
        int r0 = nBase + wr * 64 + i * 16 + (l >> 2);
        float xs0 = g_xsq[r0];
        float xs1 = g_xsq[r0 + 8];
#pragma unroll
        for (int j = 0; j < 4; ++j) {
            int col = mBase + wc * 32 + j * 8 + 2 * (l & 3);
            if (col < MM) {
                float2 zz = *reinterpret_cast<const float2*>(&g_zsq[col]);
                float d00 = fmaf(-2.f, c[i][j][0], xs0 + zz.x);
                float d01 = fmaf(-2.f, c[i][j][1], xs0 + zz.y);
                float d10 = fmaf(-2.f, c[i][j][2], xs1 + zz.x);
                float d11 = fmaf(-2.f, c[i][j][3], xs1 + zz.y);
                float v00 = ex2_ap(sqrt_ap(fmaxf(d00, 0.f)) * negscale);
                float v01 = ex2_ap(sqrt_ap(fmaxf(d01, 0.f)) * negscale);
                float v10 = ex2_ap(sqrt_ap(fmaxf(d10, 0.f)) * negscale);
                float v11 = ex2_ap(sqrt_ap(fmaxf(d11, 0.f)) * negscale);
                *reinterpret_cast<__half2*>(g_kh + (size_t)r0 * MM + col) =
                    __floats2half2_rn(v00, v01);
                *reinterpret_cast<__half2*>(g_kh + (size_t)(r0 + 8) * MM + col) =
                    __floats2half2_rn(v10, v11);
            }
        }
    }
}

// ============== GEMM2: fp16 mma.sync out = kmat @ W ==============
// 64n x 256y tile, BK=32, 256 threads, 8 warps (2x4), warp 32x64, 4 stages.
#define NCH2 (MM / 32)              // 625
#define S2 ((64 + 256) * ST)        // 25600 B per stage
#define SMEM2 (4 * S2)              // 102400 B

__device__ __forceinline__ void g2_copy(uint32_t stage, int kc,
                                        int tid, int nBase) {
    int s = tid & 3;
    {
        int row = tid >> 2;  // 0..63
        const char* asrc = reinterpret_cast<const char*>(g_kh) +
                           ((size_t)(nBase + row) * MM + (size_t)kc * 32) * 2;
        cp16(stage + row * ST + s * 16, asrc + s * 16);
    }
#pragma unroll
    for (int i = 0; i < 4; ++i) {
        int row = (tid >> 2) + i * 64;  // 0..255 (y)
        const char* bsrc = reinterpret_cast<const char*>(g_wth) +
                           ((size_t)row * MM + (size_t)kc * 32) * 2;
        cp16(stage + 64 * ST + row * ST + s * 16, bsrc + s * 16);
    }
    cp_commit();
}

__global__ __launch_bounds__(256)
void out_mma_kernel(float* __restrict__ Out) {
    extern __shared__ __align__(16) char sm2[];

    const int tid = threadIdx.x;
    const int l = tid & 31;
    const int wid = tid >> 5;
    const int wr = wid >> 2;   // 0..1 (n)
    const int wc = wid & 3;    // 0..3 (y)
    const int nBase = blockIdx.x * 64;
    const uint32_t base = s2u(sm2);

    float c[2][8][4];
#pragma unroll
    for (int i = 0; i < 2; ++i)
#pragma unroll
        for (int j = 0; j < 8; ++j)
#pragma unroll
            for (int q = 0; q < 4; ++q) c[i][j][q] = 0.f;

    g2_copy(base + 0 * S2, 0, tid, nBase);
    g2_copy(base + 1 * S2, 1, tid, nBase);
    g2_copy(base + 2 * S2, 2, tid, nBase);

    for (int kc = 0; kc < NCH2; ++kc) {
        if (kc < NCH2 - 2) cp_wait<2>();
        else if (kc == NCH2 - 2) cp_wait<1>();
        else cp_wait<0>();
        __syncthreads();
        if (kc + 3 < NCH2)
            g2_copy(base + (uint32_t)((kc + 3) & 3) * S2, kc + 3, tid, nBase);

        uint32_t aS = base + (uint32_t)(kc & 3) * S2;
        uint32_t bS = aS + 64 * ST;
#pragma unroll
        for (int ks = 0; ks < 2; ++ks) {
            int koff = ks * 32;
            uint32_t a[2][4];
#pragma unroll
            for (int i = 0; i < 2; ++i)
                ldm_x4(a[i][0], a[i][1], a[i][2], a[i][3],
                       aS + (wr * 32 + i * 16 + (l & 15)) * ST + koff + ((l >> 4) << 4));
            uint32_t b[8][2];
#pragma unroll
            for (int j = 0; j < 8; ++j)
                ldm_x2(b[j][0], b[j][1],
                       bS + (wc * 64 + j * 8 + (l & 7)) * ST + koff + (((l >> 3) & 1) << 4));
#pragma unroll
            for (int i = 0; i < 2; ++i)
#pragma unroll
                for (int j = 0; j < 8; ++j)
                    mma_f16(c[i][j], a[i][0], a[i][1], a[i][2], a[i][3],
                            b[j][0], b[j][1]);
        }
    }

#pragma unroll
    for (int i = 0; i < 2; ++i) {
        int r0 = nBase + wr * 32 + i * 16 + (l >> 2);
#pragma unroll
        for (int j = 0; j < 8; ++j) {
            int col = wc * 64 + j * 8 + 2 * (l & 3);
            *reinterpret_cast<float2*>(Out + (size_t)r0 * YY + col) =
                make_float2(c[i][j][0], c[i][j][1]);
            *reinterpret_cast<float2*>(Out + (size_t)(r0 + 8) * YY + col) =
                make_float2(c[i][j][2], c[i][j][3]);
        }
    }
}

extern "C" void kernel_launch(void* const* d_in, const int* in_sizes, int n_in,
                              void* d_out, int out_size) {
    (void)in_sizes; (void)n_in; (void)out_size;
    const float* batch   = (const float*)d_in[0];
    const float* centers = (const float*)d_in[1];
    const float* weight  = (const float*)d_in[2];
    const int*   bwp     = (const int*)d_in[3];
    float* out = (float*)d_out;

    cudaFuncSetAttribute(kmat_mma_kernel,
                         cudaFuncAttributeMaxDynamicSharedMemorySize, SMEM1);
    cudaFuncSetAttribute(out_mma_kernel,
                         cudaFuncAttributeMaxDynamicSharedMemorySize, SMEM2);

    __nv_bfloat16* abf_p = nullptr;
    __nv_bfloat16* bbf_p = nullptr;
    float* xsq_p = nullptr;
    float* zsq_p = nullptr;
    cudaGetSymbolAddress((void**)&abf_p, g_abf);
    cudaGetSymbolAddress((void**)&bbf_p, g_bbf);
    cudaGetSymbolAddress((void**)&xsq_p, g_xsq);
    cudaGetSymbolAddress((void**)&zsq_p, g_zsq);

    cvtnorm_kernel<<<NN, 256>>>(batch, abf_p, xsq_p);
    cvtnorm_kernel<<<MM, 256>>>(centers, bbf_p, zsq_p);

    {
        dim3 b(32, 8);
        dim3 g(YY / 32, MM / 32);  // 8 x 625
        wth_kernel<<<g, b>>>(weight);
    }

    const int GM = (MM + 127) / 128;           // 157
    kmat_mma_kernel<<<GM * (NN / 128), 256, SMEM1>>>(bwp);

    out_mma_kernel<<<NN / 64, 256, SMEM2>>>(out);
}